// round 16
// baseline (speedup 1.0000x reference)
#include <cuda_runtime.h>
#include <cuda_fp16.h>
#include <mma.h>
#include <math.h>
#include <stdint.h>

using namespace nvcuda;

// Problem constants
#define NN 100000
#define DD 128
#define EE 500000
#define RR 3
#define RRNN (RR * NN)                 // 300000
#define NB1  ((RRNN + 1023) / 1024)    // 293 scan blocks
#define HB   ((EE + 255) / 256)        // 1954 hist blocks per relation
#define CVB  ((NN * 32 + 255) / 256)   // 12500 convert blocks

// ---------------------------------------------------------------------------
// Static device scratch (allocation-free rule)
// ---------------------------------------------------------------------------
__device__ __half g_x16[(size_t)NN * DD];        // 25.6 MB (gather source, L2-resident)
__device__ __half g_xagg[(size_t)RR * NN * DD];  // 76.8 MB (aggregated x, fp16)
__device__ float  g_vl[RR * DD];                 // W_r^T al_r
__device__ float  g_vr[RR * DD];                 // W_r^T ar_r
__device__ float  g_el[RRNN];
__device__ float  g_er[RRNN];
__device__ int    g_cnt[RRNN];
__device__ int    g_off[RRNN];
__device__ int    g_cur[RRNN];
__device__ int    g_bsum[NB1];
__device__ int    g_csrc[(size_t)RR * EE];
__device__ float  g_wcsr[(size_t)RR * EE];       // per-edge exp(e), CSR order

union HPack8 { __half h[8]; uint4 u; };

// ---------------------------------------------------------------------------
// Launch 1 (fused): blocks [0,NB1) zero g_cnt; blocks [NB1,NB1+RR) compute
// vl_r = W_r^T al_r, vr_r = W_r^T ar_r. Independent outputs, one launch.
// ---------------------------------------------------------------------------
__global__ void prep_zero_kernel(const float* __restrict__ W,
                                 const float* __restrict__ al,
                                 const float* __restrict__ ar)
{
    if (blockIdx.x < NB1) {
        const int base = blockIdx.x * 1024 + threadIdx.x * 4;
#pragma unroll
        for (int j = 0; j < 4; j++)
            if (base + j < RRNN) g_cnt[base + j] = 0;
    } else {
        const int r = blockIdx.x - NB1;
        const int j = threadIdx.x;
        if (j < DD) {
            const float* Wr = W + (size_t)r * DD * DD;
            float sl = 0.f, sr = 0.f;
            for (int n = 0; n < DD; n++) {
                float w = __ldg(Wr + (size_t)n * DD + j);
                sl += __ldg(al + r * DD + n) * w;
                sr += __ldg(ar + r * DD + n) * w;
            }
            g_vl[r * DD + j] = sl;
            g_vr[r * DD + j] = sr;
        }
    }
}

// ---------------------------------------------------------------------------
// Launch 2 (fused): blocks [0,CVB) convert x->x16 + el/er gemv (warp/row);
// blocks [CVB, CVB+RR*HB) histogram dst counts. Both depend only on launch 1.
// ---------------------------------------------------------------------------
__global__ void __launch_bounds__(256) convert_hist_kernel(
    const float* __restrict__ x, const int* __restrict__ dst)
{
    if (blockIdx.x < CVB) {
        const int row  = (blockIdx.x * 256 + threadIdx.x) >> 5;
        const int lane = threadIdx.x & 31;
        if (row >= NN) return;
        const int c0 = lane * 4;

        float4 v = __ldg((const float4*)(x + (size_t)row * DD + c0));
        __half2 h01 = __float22half2_rn(make_float2(v.x, v.y));
        __half2 h23 = __float22half2_rn(make_float2(v.z, v.w));
        *(uint2*)(g_x16 + (size_t)row * DD + c0) =
            make_uint2(*(uint32_t*)&h01, *(uint32_t*)&h23);

#pragma unroll
        for (int r = 0; r < RR; r++) {
            const float* vl = g_vl + r * DD + c0;
            const float* vr = g_vr + r * DD + c0;
            float el = v.x * vl[0] + v.y * vl[1] + v.z * vl[2] + v.w * vl[3];
            float er = v.x * vr[0] + v.y * vr[1] + v.z * vr[2] + v.w * vr[3];
#pragma unroll
            for (int off = 16; off > 0; off >>= 1) {
                el += __shfl_xor_sync(0xffffffffu, el, off);
                er += __shfl_xor_sync(0xffffffffu, er, off);
            }
            if (lane == 0) {
                g_el[r * NN + row] = el;
                g_er[r * NN + row] = er;
            }
        }
    } else {
        const int hb = blockIdx.x - CVB;      // 0 .. RR*HB-1
        const int r  = hb / HB;
        const int i  = (hb % HB) * 256 + threadIdx.x;
        if (i < EE)
            atomicAdd(g_cnt + r * NN + dst[(size_t)r * EE + i], 1);
    }
}

// ---------------------------------------------------------------------------
// CSR scans: scan1 (per-block) -> scan23 (merged cross-block + cursor init)
// ---------------------------------------------------------------------------
__global__ void scan1_kernel()
{
    __shared__ int s[256];
    const int tid  = threadIdx.x;
    const int base = blockIdx.x * 1024 + tid * 4;
    int v[4], run = 0;
#pragma unroll
    for (int j = 0; j < 4; j++) {
        v[j] = (base + j < RRNN) ? g_cnt[base + j] : 0;
        run += v[j];
    }
    s[tid] = run;
    __syncthreads();
    int val = run;
    for (int off = 1; off < 256; off <<= 1) {
        int x = (tid >= off) ? s[tid - off] : 0;
        __syncthreads();
        s[tid] = val = val + x;
        __syncthreads();
    }
    int excl = s[tid] - run;
#pragma unroll
    for (int j = 0; j < 4; j++) {
        if (base + j < RRNN) g_off[base + j] = excl;
        excl += v[j];
    }
    if (tid == 255) g_bsum[blockIdx.x] = s[255];
}

__global__ void scan23_kernel()
{
    __shared__ int wsum[8];
    const int tid = threadIdx.x;                 // 256
    const int b   = blockIdx.x;

    int partial = 0;
    for (int i = tid; i < b; i += 256) partial += g_bsum[i];
#pragma unroll
    for (int off = 16; off > 0; off >>= 1)
        partial += __shfl_xor_sync(0xffffffffu, partial, off);
    if ((tid & 31) == 0) wsum[tid >> 5] = partial;
    __syncthreads();
    int add = 0;
#pragma unroll
    for (int k = 0; k < 8; k++) add += wsum[k];

    const int base = b * 1024 + tid * 4;
#pragma unroll
    for (int j = 0; j < 4; j++) {
        int i = base + j;
        if (i < RRNN) {
            int o = g_off[i] + add;
            g_off[i] = o;
            g_cur[i] = o;
        }
    }
}

// ---------------------------------------------------------------------------
// fill_w: CSR fill + per-edge weight w = exp(leakyrelu(el+er))
// ---------------------------------------------------------------------------
__global__ void fill_w_kernel(const int* __restrict__ src, const int* __restrict__ dst)
{
    int i = blockIdx.x * blockDim.x + threadIdx.x;
    if (i >= EE) return;
    int r   = blockIdx.y;
    int s   = src[(size_t)r * EE + i];
    int idx = r * NN + dst[(size_t)r * EE + i];
    int pos = atomicAdd(g_cur + idx, 1);
    float e = g_el[r * NN + s] + g_er[idx];
    e = e >= 0.f ? e : 0.2f * e;
    g_csrc[pos] = s;
    g_wcsr[pos] = __expf(e);
}

// ---------------------------------------------------------------------------
// Aggregation in x-space: warp per (dst node, relation) via blockIdx.y.
// Gather x16 rows with precomputed weights, write xagg fp16.
// ---------------------------------------------------------------------------
__global__ void __launch_bounds__(256) pass_agg_kernel()
{
    const int d    = (blockIdx.x * blockDim.x + threadIdx.x) >> 5;
    const int lane = threadIdx.x & 31;
    const int r    = blockIdx.y;
    if (d >= NN) return;
    const int c0 = lane * 4;

    const int idx = r * NN + d;
    const int beg = g_off[idx];
    const int end = g_cur[idx];
    float4 acc = make_float4(0.f, 0.f, 0.f, 0.f);

    if (beg != end) {
        float s = 0.f;
        for (int j = beg + lane; j < end; j += 32) s += g_wcsr[j];
#pragma unroll
        for (int off = 16; off > 0; off >>= 1)
            s += __shfl_xor_sync(0xffffffffu, s, off);
        const float inv = 1.0f / (s * 3.0f);

        int j = beg;
        for (; j + 3 < end; j += 4) {
            int   s0 = g_csrc[j],     s1 = g_csrc[j + 1],
                  s2 = g_csrc[j + 2], s3 = g_csrc[j + 3];
            float w0 = g_wcsr[j]     * inv, w1 = g_wcsr[j + 1] * inv,
                  w2 = g_wcsr[j + 2] * inv, w3 = g_wcsr[j + 3] * inv;
            uint2 p0 = *(const uint2*)(g_x16 + (size_t)s0 * DD + c0);
            uint2 p1 = *(const uint2*)(g_x16 + (size_t)s1 * DD + c0);
            uint2 p2 = *(const uint2*)(g_x16 + (size_t)s2 * DD + c0);
            uint2 p3 = *(const uint2*)(g_x16 + (size_t)s3 * DD + c0);
            float2 a01 = __half22float2(*(__half2*)&p0.x), a23 = __half22float2(*(__half2*)&p0.y);
            float2 b01 = __half22float2(*(__half2*)&p1.x), b23 = __half22float2(*(__half2*)&p1.y);
            float2 c01 = __half22float2(*(__half2*)&p2.x), c23 = __half22float2(*(__half2*)&p2.y);
            float2 d01 = __half22float2(*(__half2*)&p3.x), d23 = __half22float2(*(__half2*)&p3.y);
            acc.x += w0 * a01.x + w1 * b01.x + w2 * c01.x + w3 * d01.x;
            acc.y += w0 * a01.y + w1 * b01.y + w2 * c01.y + w3 * d01.y;
            acc.z += w0 * a23.x + w1 * b23.x + w2 * c23.x + w3 * d23.x;
            acc.w += w0 * a23.y + w1 * b23.y + w2 * c23.y + w3 * d23.y;
        }
        for (; j < end; j++) {
            int   sj = g_csrc[j];
            float w  = g_wcsr[j] * inv;
            uint2 p0 = *(const uint2*)(g_x16 + (size_t)sj * DD + c0);
            float2 a01 = __half22float2(*(__half2*)&p0.x);
            float2 a23 = __half22float2(*(__half2*)&p0.y);
            acc.x += w * a01.x; acc.y += w * a01.y;
            acc.z += w * a23.x; acc.w += w * a23.y;
        }
    }
    __half2 h01 = __float22half2_rn(make_float2(acc.x, acc.y));
    __half2 h23 = __float22half2_rn(make_float2(acc.z, acc.w));
    *(uint2*)(g_xagg + ((size_t)r * NN + d) * DD + c0) =
        make_uint2(*(uint32_t*)&h01, *(uint32_t*)&h23);
}

// ---------------------------------------------------------------------------
// Final projection: out = sum_r xagg_r @ W_r^T + bias_mean.
// fp16 single-term MMA; acc persists ACROSS relations; one epilogue.
// M-tile 64, 256 threads (8 warps 2x4), 3 CTAs/SM.
// ---------------------------------------------------------------------------
#define MT    64
#define LDT   136
#define LDC   132
#define SM_A  0
#define SM_B  (MT * LDT * 2)           // 17408
#define SM_TOT (SM_B + 128 * LDT * 2)  // 52224

__device__ __forceinline__ void cvt8h(const float* __restrict__ p, HPack8& hv)
{
    float4 v0 = __ldg((const float4*)p);
    float4 v1 = __ldg((const float4*)(p + 4));
    float wv[8] = {v0.x, v0.y, v0.z, v0.w, v1.x, v1.y, v1.z, v1.w};
#pragma unroll
    for (int j = 0; j < 8; j++) hv.h[j] = __float2half_rn(wv[j]);
}

__global__ void __launch_bounds__(256, 3) out_gemm_kernel(
    const float* __restrict__ W, const float* __restrict__ bias,
    float* __restrict__ out)
{
    extern __shared__ char smraw[];
    __half* smA = (__half*)(smraw + SM_A);
    __half* smB = (__half*)(smraw + SM_B);
    float*  smC = (float*)(smraw + SM_B);   // aliased over B

    const int tid  = threadIdx.x;
    const int wid  = tid >> 5;
    const int lane = tid & 31;
    const int row0 = blockIdx.x * MT;
    const int wm   = wid >> 2;
    const int wn   = wid & 3;

    wmma::fragment<wmma::accumulator, 16, 16, 16, float> acc[2][2];
#pragma unroll
    for (int mi = 0; mi < 2; mi++)
#pragma unroll
        for (int ni = 0; ni < 2; ni++) wmma::fill_fragment(acc[mi][ni], 0.0f);

    for (int rel = 0; rel < RR; rel++) {
#pragma unroll
        for (int t = 0; t < 4; t++) {
            int idx  = tid + t * 256;        // 64 rows x 16 chunks
            int row  = idx >> 4;
            int k8   = (idx & 15) << 3;
            int grow = row0 + row;
            uint4 v = make_uint4(0u, 0u, 0u, 0u);
            if (grow < NN)
                v = *(const uint4*)(g_xagg + ((size_t)rel * NN + grow) * DD + k8);
            *(uint4*)(smA + row * LDT + k8) = v;
        }
        const float* Wr = W + (size_t)rel * DD * DD;
#pragma unroll
        for (int t = 0; t < 8; t++) {
            int idx = tid + t * 256;         // 128 rows x 16 chunks
            int n   = idx >> 4;
            int k8  = (idx & 15) << 3;
            HPack8 hv;
            cvt8h(Wr + (size_t)n * DD + k8, hv);
            *(uint4*)(smB + n * LDT + k8) = hv.u;
        }
        __syncthreads();

#pragma unroll 2
        for (int kk = 0; kk < DD; kk += 16) {
            wmma::fragment<wmma::matrix_a, 16, 16, 16, __half, wmma::row_major> af[2];
            wmma::fragment<wmma::matrix_b, 16, 16, 16, __half, wmma::col_major> bf[2];
#pragma unroll
            for (int mi = 0; mi < 2; mi++)
                wmma::load_matrix_sync(af[mi], smA + (wm * 32 + mi * 16) * LDT + kk, LDT);
#pragma unroll
            for (int ni = 0; ni < 2; ni++)
                wmma::load_matrix_sync(bf[ni], smB + (wn * 32 + ni * 16) * LDT + kk, LDT);
#pragma unroll
            for (int mi = 0; mi < 2; mi++)
#pragma unroll
                for (int ni = 0; ni < 2; ni++)
                    wmma::mma_sync(acc[mi][ni], af[mi], bf[ni], acc[mi][ni]);
        }
        __syncthreads();
    }

#pragma unroll
    for (int mi = 0; mi < 2; mi++)
#pragma unroll
        for (int ni = 0; ni < 2; ni++)
            wmma::store_matrix_sync(smC + (wm * 32 + mi * 16) * LDC + wn * 32 + ni * 16,
                                    acc[mi][ni], LDC, wmma::mem_row_major);
    __syncthreads();

    const int c0 = lane * 4;
    float4 bmean;
    bmean.x = (__ldg(bias + c0)     + __ldg(bias + DD + c0)     + __ldg(bias + 2 * DD + c0))     * (1.f / 3.f);
    bmean.y = (__ldg(bias + c0 + 1) + __ldg(bias + DD + c0 + 1) + __ldg(bias + 2 * DD + c0 + 1)) * (1.f / 3.f);
    bmean.z = (__ldg(bias + c0 + 2) + __ldg(bias + DD + c0 + 2) + __ldg(bias + 2 * DD + c0 + 2)) * (1.f / 3.f);
    bmean.w = (__ldg(bias + c0 + 3) + __ldg(bias + DD + c0 + 3) + __ldg(bias + 2 * DD + c0 + 3)) * (1.f / 3.f);

#pragma unroll
    for (int rr = 0; rr < 8; rr++) {
        int row  = wid * 8 + rr;
        int grow = row0 + row;
        if (grow < NN) {
            float4 v = *(const float4*)(smC + row * LDC + c0);
            v.x += bmean.x; v.y += bmean.y; v.z += bmean.z; v.w += bmean.w;
            *(float4*)(out + (size_t)grow * DD + c0) = v;
        }
    }
}

// ---------------------------------------------------------------------------
// Launch: single stream, 7 kernels (fused prep+zero, fused convert+hist)
// ---------------------------------------------------------------------------
extern "C" void kernel_launch(void* const* d_in, const int* in_sizes, int n_in,
                              void* d_out, int out_size)
{
    const float* x    = (const float*)d_in[0];
    const int*   src  = (const int*)  d_in[1];
    const int*   dst  = (const int*)  d_in[2];
    const float* W    = (const float*)d_in[3];
    const float* al   = (const float*)d_in[4];
    const float* ar   = (const float*)d_in[5];
    const float* bias = (const float*)d_in[6];
    float* out = (float*)d_out;

    cudaFuncSetAttribute(out_gemm_kernel, cudaFuncAttributeMaxDynamicSharedMemorySize, SM_TOT);

    prep_zero_kernel<<<NB1 + RR, 256>>>(W, al, ar);
    convert_hist_kernel<<<CVB + RR * HB, 256>>>(x, dst);
    scan1_kernel<<<NB1, 256>>>();
    scan23_kernel<<<NB1, 256>>>();
    fill_w_kernel<<<dim3(HB, RR), 256>>>(src, dst);
    pass_agg_kernel<<<dim3(CVB, RR), 256>>>();
    out_gemm_kernel<<<(NN + MT - 1) / MT, 256, SM_TOT>>>(W, bias, out);
}

// round 17
// speedup vs baseline: 1.0865x; 1.0865x over previous
#include <cuda_runtime.h>
#include <cuda_fp16.h>
#include <mma.h>
#include <math.h>
#include <stdint.h>

using namespace nvcuda;

// Problem constants
#define NN 100000
#define DD 128
#define EE 500000
#define RR 3
#define RRNN (RR * NN)                 // 300000
#define NB1  ((RRNN + 1023) / 1024)    // 293 scan blocks

// ---------------------------------------------------------------------------
// Static device scratch (allocation-free rule)
// ---------------------------------------------------------------------------
__device__ __half g_x16[(size_t)NN * DD];        // 25.6 MB (gather source, L2-resident)
__device__ __half g_xagg[(size_t)RR * NN * DD];  // 76.8 MB (aggregated x, fp16)
__device__ __half g_w16[(size_t)RR * DD * DD];   // 96 KB (W in fp16, converted once)
__device__ float  g_vl[RR * DD];                 // W_r^T al_r
__device__ float  g_vr[RR * DD];                 // W_r^T ar_r
__device__ float  g_el[RRNN];
__device__ float  g_er[RRNN];
__device__ int    g_cnt[RRNN];
__device__ int    g_off[RRNN];
__device__ int    g_cur[RRNN];
__device__ int    g_bsum[NB1];
__device__ int    g_csrc[(size_t)RR * EE];
__device__ float  g_wcsr[(size_t)RR * EE];       // per-edge exp(e), CSR order

union HPack8 { __half h[8]; uint4 u; };

__device__ __forceinline__ void cvt8h(const float* __restrict__ p, HPack8& hv)
{
    float4 v0 = __ldg((const float4*)p);
    float4 v1 = __ldg((const float4*)(p + 4));
    float wv[8] = {v0.x, v0.y, v0.z, v0.w, v1.x, v1.y, v1.z, v1.w};
#pragma unroll
    for (int j = 0; j < 8; j++) hv.h[j] = __float2half_rn(wv[j]);
}

// ---------------------------------------------------------------------------
// prep: per relation block — vl_r = W_r^T al_r, vr_r = W_r^T ar_r (threads
// 0..127) AND W_r fp32 -> fp16 into g_w16 (all 256 threads). One-time cost.
// ---------------------------------------------------------------------------
__global__ void prep_vlvr_kernel(const float* __restrict__ W,
                                 const float* __restrict__ al,
                                 const float* __restrict__ ar)
{
    const int r   = blockIdx.x;
    const int tid = threadIdx.x;          // 256
    const float* Wr = W + (size_t)r * DD * DD;

    // W -> fp16 (16384 elems / 256 threads = 8 chunks of 8)
    for (int idx = tid; idx < DD * DD / 8; idx += 256) {
        HPack8 hv;
        cvt8h(Wr + idx * 8, hv);
        *(uint4*)(g_w16 + (size_t)r * DD * DD + idx * 8) = hv.u;
    }

    if (tid < DD) {
        const int j = tid;                // k index
        float sl = 0.f, sr = 0.f;
        for (int n = 0; n < DD; n++) {
            float w = __ldg(Wr + (size_t)n * DD + j);
            sl += __ldg(al + r * DD + n) * w;
            sr += __ldg(ar + r * DD + n) * w;
        }
        g_vl[r * DD + j] = sl;
        g_vr[r * DD + j] = sr;
    }
}

// ---------------------------------------------------------------------------
// convert + gemv: one pass over x — write x16 (fp16) and el/er for all rels.
// Warp per row.
// ---------------------------------------------------------------------------
__global__ void __launch_bounds__(256) convert_gemv_kernel(const float* __restrict__ x)
{
    const int row  = (blockIdx.x * blockDim.x + threadIdx.x) >> 5;
    const int lane = threadIdx.x & 31;
    if (row >= NN) return;
    const int c0 = lane * 4;

    float4 v = __ldg((const float4*)(x + (size_t)row * DD + c0));
    __half2 h01 = __float22half2_rn(make_float2(v.x, v.y));
    __half2 h23 = __float22half2_rn(make_float2(v.z, v.w));
    *(uint2*)(g_x16 + (size_t)row * DD + c0) =
        make_uint2(*(uint32_t*)&h01, *(uint32_t*)&h23);

#pragma unroll
    for (int r = 0; r < RR; r++) {
        const float* vl = g_vl + r * DD + c0;
        const float* vr = g_vr + r * DD + c0;
        float el = v.x * vl[0] + v.y * vl[1] + v.z * vl[2] + v.w * vl[3];
        float er = v.x * vr[0] + v.y * vr[1] + v.z * vr[2] + v.w * vr[3];
#pragma unroll
        for (int off = 16; off > 0; off >>= 1) {
            el += __shfl_xor_sync(0xffffffffu, el, off);
            er += __shfl_xor_sync(0xffffffffu, er, off);
        }
        if (lane == 0) {
            g_el[r * NN + row] = el;
            g_er[r * NN + row] = er;
        }
    }
}

// ---------------------------------------------------------------------------
// CSR build: zero -> histogram -> scan1 -> scan23(merged)
// ---------------------------------------------------------------------------
__global__ void zero_cnt_kernel()
{
    int i = blockIdx.x * blockDim.x + threadIdx.x;
    if (i < RRNN) g_cnt[i] = 0;
}

__global__ void hist_kernel(const int* __restrict__ dst)
{
    int i = blockIdx.x * blockDim.x + threadIdx.x;
    if (i >= RR * EE) return;
    int r = i / EE;
    atomicAdd(g_cnt + r * NN + dst[i], 1);
}

__global__ void scan1_kernel()
{
    __shared__ int s[256];
    const int tid  = threadIdx.x;
    const int base = blockIdx.x * 1024 + tid * 4;
    int v[4], run = 0;
#pragma unroll
    for (int j = 0; j < 4; j++) {
        v[j] = (base + j < RRNN) ? g_cnt[base + j] : 0;
        run += v[j];
    }
    s[tid] = run;
    __syncthreads();
    int val = run;
    for (int off = 1; off < 256; off <<= 1) {
        int x = (tid >= off) ? s[tid - off] : 0;
        __syncthreads();
        s[tid] = val = val + x;
        __syncthreads();
    }
    int excl = s[tid] - run;
#pragma unroll
    for (int j = 0; j < 4; j++) {
        if (base + j < RRNN) g_off[base + j] = excl;
        excl += v[j];
    }
    if (tid == 255) g_bsum[blockIdx.x] = s[255];
}

__global__ void scan23_kernel()
{
    __shared__ int wsum[8];
    const int tid = threadIdx.x;                 // 256
    const int b   = blockIdx.x;

    int partial = 0;
    for (int i = tid; i < b; i += 256) partial += g_bsum[i];
#pragma unroll
    for (int off = 16; off > 0; off >>= 1)
        partial += __shfl_xor_sync(0xffffffffu, partial, off);
    if ((tid & 31) == 0) wsum[tid >> 5] = partial;
    __syncthreads();
    int add = 0;
#pragma unroll
    for (int k = 0; k < 8; k++) add += wsum[k];

    const int base = b * 1024 + tid * 4;
#pragma unroll
    for (int j = 0; j < 4; j++) {
        int i = base + j;
        if (i < RRNN) {
            int o = g_off[i] + add;
            g_off[i] = o;
            g_cur[i] = o;
        }
    }
}

// ---------------------------------------------------------------------------
// fill_w: CSR fill + per-edge weight w = exp(leakyrelu(el+er))
// ---------------------------------------------------------------------------
__global__ void fill_w_kernel(const int* __restrict__ src, const int* __restrict__ dst)
{
    int i = blockIdx.x * blockDim.x + threadIdx.x;
    if (i >= RR * EE) return;
    int r   = i / EE;
    int s   = src[i];
    int idx = r * NN + dst[i];
    int pos = atomicAdd(g_cur + idx, 1);
    float e = g_el[r * NN + s] + g_er[idx];
    e = e >= 0.f ? e : 0.2f * e;
    g_csrc[pos] = s;
    g_wcsr[pos] = __expf(e);
}

// ---------------------------------------------------------------------------
// Aggregation in x-space: warp per dst node, loops all relations.
// Gather x16 rows with precomputed weights, write xagg fp16.
// ---------------------------------------------------------------------------
__global__ void __launch_bounds__(256) pass_agg_kernel()
{
    const int d    = (blockIdx.x * blockDim.x + threadIdx.x) >> 5;
    const int lane = threadIdx.x & 31;
    if (d >= NN) return;
    const int c0 = lane * 4;

#pragma unroll
    for (int r = 0; r < RR; r++) {
        const int idx = r * NN + d;
        const int beg = g_off[idx];
        const int end = g_cur[idx];
        float4 acc = make_float4(0.f, 0.f, 0.f, 0.f);

        if (beg != end) {
            float s = 0.f;
            for (int j = beg + lane; j < end; j += 32) s += g_wcsr[j];
#pragma unroll
            for (int off = 16; off > 0; off >>= 1)
                s += __shfl_xor_sync(0xffffffffu, s, off);
            const float inv = 1.0f / (s * 3.0f);

            int j = beg;
            for (; j + 3 < end; j += 4) {
                int   s0 = g_csrc[j],     s1 = g_csrc[j + 1],
                      s2 = g_csrc[j + 2], s3 = g_csrc[j + 3];
                float w0 = g_wcsr[j]     * inv, w1 = g_wcsr[j + 1] * inv,
                      w2 = g_wcsr[j + 2] * inv, w3 = g_wcsr[j + 3] * inv;
                uint2 p0 = *(const uint2*)(g_x16 + (size_t)s0 * DD + c0);
                uint2 p1 = *(const uint2*)(g_x16 + (size_t)s1 * DD + c0);
                uint2 p2 = *(const uint2*)(g_x16 + (size_t)s2 * DD + c0);
                uint2 p3 = *(const uint2*)(g_x16 + (size_t)s3 * DD + c0);
                float2 a01 = __half22float2(*(__half2*)&p0.x), a23 = __half22float2(*(__half2*)&p0.y);
                float2 b01 = __half22float2(*(__half2*)&p1.x), b23 = __half22float2(*(__half2*)&p1.y);
                float2 c01 = __half22float2(*(__half2*)&p2.x), c23 = __half22float2(*(__half2*)&p2.y);
                float2 d01 = __half22float2(*(__half2*)&p3.x), d23 = __half22float2(*(__half2*)&p3.y);
                acc.x += w0 * a01.x + w1 * b01.x + w2 * c01.x + w3 * d01.x;
                acc.y += w0 * a01.y + w1 * b01.y + w2 * c01.y + w3 * d01.y;
                acc.z += w0 * a23.x + w1 * b23.x + w2 * c23.x + w3 * d23.x;
                acc.w += w0 * a23.y + w1 * b23.y + w2 * c23.y + w3 * d23.y;
            }
            for (; j < end; j++) {
                int   sj = g_csrc[j];
                float w  = g_wcsr[j] * inv;
                uint2 p0 = *(const uint2*)(g_x16 + (size_t)sj * DD + c0);
                float2 a01 = __half22float2(*(__half2*)&p0.x);
                float2 a23 = __half22float2(*(__half2*)&p0.y);
                acc.x += w * a01.x; acc.y += w * a01.y;
                acc.z += w * a23.x; acc.w += w * a23.y;
            }
        }
        __half2 h01 = __float22half2_rn(make_float2(acc.x, acc.y));
        __half2 h23 = __float22half2_rn(make_float2(acc.z, acc.w));
        *(uint2*)(g_xagg + ((size_t)r * NN + d) * DD + c0) =
            make_uint2(*(uint32_t*)&h01, *(uint32_t*)&h23);
    }
}

// ---------------------------------------------------------------------------
// Final projection: out = sum_r xagg_r @ W_r^T + bias_mean.
// fp16 single-term MMA; acc persists ACROSS relations; one epilogue.
// B loaded from pre-converted g_w16 (uint4 copy, no per-CTA fp32 reads/cvt).
// M-tile 64, 256 threads (8 warps 2x4), 3 CTAs/SM.
// ---------------------------------------------------------------------------
#define MT    64
#define LDT   136
#define LDC   132
#define SM_A  0
#define SM_B  (MT * LDT * 2)           // 17408
#define SM_TOT (SM_B + 128 * LDT * 2)  // 52224

__global__ void __launch_bounds__(256, 3) out_gemm_kernel(
    const float* __restrict__ bias, float* __restrict__ out)
{
    extern __shared__ char smraw[];
    __half* smA = (__half*)(smraw + SM_A);
    __half* smB = (__half*)(smraw + SM_B);
    float*  smC = (float*)(smraw + SM_B);   // aliased over B

    const int tid  = threadIdx.x;
    const int wid  = tid >> 5;
    const int lane = tid & 31;
    const int row0 = blockIdx.x * MT;
    const int wm   = wid >> 2;
    const int wn   = wid & 3;

    wmma::fragment<wmma::accumulator, 16, 16, 16, float> acc[2][2];
#pragma unroll
    for (int mi = 0; mi < 2; mi++)
#pragma unroll
        for (int ni = 0; ni < 2; ni++) wmma::fill_fragment(acc[mi][ni], 0.0f);

    for (int rel = 0; rel < RR; rel++) {
#pragma unroll
        for (int t = 0; t < 4; t++) {
            int idx  = tid + t * 256;        // 64 rows x 16 chunks
            int row  = idx >> 4;
            int k8   = (idx & 15) << 3;
            int grow = row0 + row;
            uint4 v = make_uint4(0u, 0u, 0u, 0u);
            if (grow < NN)
                v = *(const uint4*)(g_xagg + ((size_t)rel * NN + grow) * DD + k8);
            *(uint4*)(smA + row * LDT + k8) = v;
        }
        const __half* W16r = g_w16 + (size_t)rel * DD * DD;
#pragma unroll
        for (int t = 0; t < 8; t++) {
            int idx = tid + t * 256;         // 128 rows x 16 chunks
            int n   = idx >> 4;
            int k8  = (idx & 15) << 3;
            *(uint4*)(smB + n * LDT + k8) = *(const uint4*)(W16r + (size_t)n * DD + k8);
        }
        __syncthreads();

#pragma unroll 2
        for (int kk = 0; kk < DD; kk += 16) {
            wmma::fragment<wmma::matrix_a, 16, 16, 16, __half, wmma::row_major> af[2];
            wmma::fragment<wmma::matrix_b, 16, 16, 16, __half, wmma::col_major> bf[2];
#pragma unroll
            for (int mi = 0; mi < 2; mi++)
                wmma::load_matrix_sync(af[mi], smA + (wm * 32 + mi * 16) * LDT + kk, LDT);
#pragma unroll
            for (int ni = 0; ni < 2; ni++)
                wmma::load_matrix_sync(bf[ni], smB + (wn * 32 + ni * 16) * LDT + kk, LDT);
#pragma unroll
            for (int mi = 0; mi < 2; mi++)
#pragma unroll
                for (int ni = 0; ni < 2; ni++)
                    wmma::mma_sync(acc[mi][ni], af[mi], bf[ni], acc[mi][ni]);
        }
        __syncthreads();
    }

#pragma unroll
    for (int mi = 0; mi < 2; mi++)
#pragma unroll
        for (int ni = 0; ni < 2; ni++)
            wmma::store_matrix_sync(smC + (wm * 32 + mi * 16) * LDC + wn * 32 + ni * 16,
                                    acc[mi][ni], LDC, wmma::mem_row_major);
    __syncthreads();

    const int c0 = lane * 4;
    float4 bmean;
    bmean.x = (__ldg(bias + c0)     + __ldg(bias + DD + c0)     + __ldg(bias + 2 * DD + c0))     * (1.f / 3.f);
    bmean.y = (__ldg(bias + c0 + 1) + __ldg(bias + DD + c0 + 1) + __ldg(bias + 2 * DD + c0 + 1)) * (1.f / 3.f);
    bmean.z = (__ldg(bias + c0 + 2) + __ldg(bias + DD + c0 + 2) + __ldg(bias + 2 * DD + c0 + 2)) * (1.f / 3.f);
    bmean.w = (__ldg(bias + c0 + 3) + __ldg(bias + DD + c0 + 3) + __ldg(bias + 2 * DD + c0 + 3)) * (1.f / 3.f);

#pragma unroll
    for (int rr = 0; rr < 8; rr++) {
        int row  = wid * 8 + rr;
        int grow = row0 + row;
        if (grow < NN) {
            float4 v = *(const float4*)(smC + row * LDC + c0);
            v.x += bmean.x; v.y += bmean.y; v.z += bmean.z; v.w += bmean.w;
            *(float4*)(out + (size_t)grow * DD + c0) = v;
        }
    }
}

// ---------------------------------------------------------------------------
// Launch (exact R12 structure; W pre-converted once in prep)
// ---------------------------------------------------------------------------
extern "C" void kernel_launch(void* const* d_in, const int* in_sizes, int n_in,
                              void* d_out, int out_size)
{
    const float* x    = (const float*)d_in[0];
    const int*   src  = (const int*)  d_in[1];
    const int*   dst  = (const int*)  d_in[2];
    const float* W    = (const float*)d_in[3];
    const float* al   = (const float*)d_in[4];
    const float* ar   = (const float*)d_in[5];
    const float* bias = (const float*)d_in[6];
    float* out = (float*)d_out;

    cudaFuncSetAttribute(out_gemm_kernel, cudaFuncAttributeMaxDynamicSharedMemorySize, SM_TOT);

    prep_vlvr_kernel<<<RR, 256>>>(W, al, ar);
    convert_gemv_kernel<<<(NN * 32 + 255) / 256, 256>>>(x);

    zero_cnt_kernel<<<(RRNN + 255) / 256, 256>>>();
    hist_kernel<<<(RR * EE + 255) / 256, 256>>>(dst);
    scan1_kernel<<<NB1, 256>>>();
    scan23_kernel<<<NB1, 256>>>();

    fill_w_kernel<<<(RR * EE + 255) / 256, 256>>>(src, dst);
    pass_agg_kernel<<<(NN * 32 + 255) / 256, 256>>>();
    out_gemm_kernel<<<(NN + MT - 1) / MT, 256, SM_TOT>>>(bias, out);
}